// round 4
// baseline (speedup 1.0000x reference)
#include <cuda_runtime.h>
#include <cstdio>

// Problem constants
#define B_ROWS   65536
#define F_DIM    512
#define H_DIM    256
#define A_DIM    4
#define E_DIM    32

#define SENT     0xFFFFFFFFu
#define IDX_LEN  65792           // 65536 + 256 pad
#define W_M_SZ   (3 * 2560)      // folded M matrices, swizzled layout
#define W_MP_OFF 7680            // Mp[2][5]
#define W_B_OFF  7690            // bias[3][5]
#define W_ME_OFF 7712            // Me[32][5] scratch (not copied to smem)
#define W_TOTAL  7872
#define SMEM_W   7712            // floats copied to shared (7705 used, padded)

// Scratch (no allocations allowed -> device globals)
__device__ float    g_W[W_TOTAL];
__device__ unsigned g_idx[IDX_LEN];
__device__ int      g_blockCnt[256 * 3];
__device__ int      g_base[256 * 3];

struct Params {
    const float *features, *pointgoal;
    const float *a0W1, *a0b1, *a0W2, *a0b2;
    const float *a1W1, *a1b1, *a1W2, *a1b2;
    const float *a2Wp, *a2bp, *a2W1, *a2b1, *a2W2, *a2b2;
    const float *c0W1, *c0b1, *c0W2, *c0b2;
    const float *c1W1, *c1b1, *c1W2, *c1b2;
    const float *c2Wp, *c2bp, *c2W1, *c2b1, *c2W2, *c2b2;
    const int   *task;
};

// 256-length dot: W1row[h] * W2[h*st] (W2 pre-offset by output column)
__device__ __forceinline__ float dot256(const float* __restrict__ w1row,
                                        const float* __restrict__ w2, int st) {
    float a0 = 0.f, a1 = 0.f, a2 = 0.f, a3 = 0.f;
#pragma unroll 8
    for (int h = 0; h < 256; h += 4) {
        float4 v = *reinterpret_cast<const float4*>(w1row + h);
        a0 = fmaf(v.x, w2[(h + 0) * st], a0);
        a1 = fmaf(v.y, w2[(h + 1) * st], a1);
        a2 = fmaf(v.z, w2[(h + 2) * st], a2);
        a3 = fmaf(v.w, w2[(h + 3) * st], a3);
    }
    return (a0 + a1) + (a2 + a3);
}

// ---------------------------------------------------------------------------
// K1: per-block task histograms + idx sentinel init + fold W1@W2 (M and Me)
// blocks [0,256): counting;  blocks [256,287): prefold
// ---------------------------------------------------------------------------
__global__ void k_count_prep(Params p) {
    if (blockIdx.x < 256) {
        int thr = threadIdx.x;
        int b = blockIdx.x * 256 + thr;
        g_idx[b] = SENT;
        if (blockIdx.x == 0) g_idx[65536 + thr] = SENT;
        int t = p.task[b];
        __shared__ int wc[8][3];
        int w = thr >> 5, lane = thr & 31;
        unsigned m0 = __ballot_sync(~0u, t == 0);
        unsigned m1 = __ballot_sync(~0u, t == 1);
        unsigned m2 = __ballot_sync(~0u, t == 2);
        if (lane == 0) { wc[w][0] = __popc(m0); wc[w][1] = __popc(m1); wc[w][2] = __popc(m2); }
        __syncthreads();
        if (thr < 3) {
            int ssum = 0;
#pragma unroll
            for (int i = 0; i < 8; i++) ssum += wc[i][thr];
            g_blockCnt[blockIdx.x * 3 + thr] = ssum;
        }
    } else {
        int idx = (blockIdx.x - 256) * 256 + threadIdx.x;
        if (idx < 7680) {
            // folded M[t][f][col], col 0 = value (critic), cols 1..4 = logits (actor)
            int t = idx / 2560;
            int r = idx - t * 2560;
            int f = r / 5, col = r - f * 5;
            const float *W1, *W2; int st, of;
            if (col == 0) {
                W1 = t == 0 ? p.c0W1 : t == 1 ? p.c1W1 : p.c2W1;
                W2 = t == 0 ? p.c0W2 : t == 1 ? p.c1W2 : p.c2W2;
                st = 1; of = 0;
            } else {
                W1 = t == 0 ? p.a0W1 : t == 1 ? p.a1W1 : p.a2W1;
                W2 = t == 0 ? p.a0W2 : t == 1 ? p.a1W2 : p.a2W2;
                st = A_DIM; of = col - 1;
            }
            float v = dot256(W1 + (size_t)f * H_DIM, W2 + of, st);
            // swizzled layout so the main kernel's LDS.128 is broadcast/conflict-free
            int j = f >> 5, ss = (f >> 2) & 7, c = f & 3;
            g_W[t * 2560 + ((j * 5 + col) * 8 + ss) * 4 + c] = v;
        } else if (idx < 7840) {
            // Me[e][col]: rows 512..543 of head-2 W1 folded with W2
            int k = idx - 7680;
            int e = k / 5, col = k - e * 5;
            const float* W1 = (col == 0) ? p.c2W1 : p.a2W1;
            const float* W2 = (col == 0) ? p.c2W2 : p.a2W2;
            int st = (col == 0) ? 1 : A_DIM, of = (col == 0) ? 0 : col - 1;
            g_W[W_ME_OFF + e * 5 + col] =
                dot256(W1 + (size_t)(512 + e) * H_DIM, W2 + of, st);
        }
    }
}

// ---------------------------------------------------------------------------
// K2: exclusive scan of per-block counts (segments padded to 16) + finalize
//     Mp = Wp @ Me and per-head bias constants. One block, 256 threads.
// ---------------------------------------------------------------------------
__global__ void k_scan_fin(Params p) {
    __shared__ int sh[256];
    __shared__ int tot[3];
    int i = threadIdx.x;
    int excl[3];
#pragma unroll
    for (int t = 0; t < 3; t++) {
        int v = g_blockCnt[i * 3 + t];
        sh[i] = v;
        __syncthreads();
        int x = v;
        for (int off = 1; off < 256; off <<= 1) {
            int y = (i >= off) ? sh[i - off] : 0;
            __syncthreads();
            x += y;
            sh[i] = x;
            __syncthreads();
        }
        excl[t] = x - v;
        if (i == 255) tot[t] = x;
        __syncthreads();
    }
    int s1 = (tot[0] + 15) & ~15;
    int s2 = s1 + ((tot[1] + 15) & ~15);
    g_base[i * 3 + 0] = excl[0];
    g_base[i * 3 + 1] = s1 + excl[1];
    g_base[i * 3 + 2] = s2 + excl[2];

    if (i < 10) {
        // Mp[pp][col] = sum_e Wp[pp][e] * Me[e][col]
        int pp = i / 5, col = i - pp * 5;
        const float* Wp = ((col == 0) ? p.c2Wp : p.a2Wp) + pp * E_DIM;
        float acc = 0.f;
        for (int e = 0; e < E_DIM; e++) acc += Wp[e] * g_W[W_ME_OFF + e * 5 + col];
        g_W[W_MP_OFF + pp * 5 + col] = acc;
    } else if (i < 25) {
        // bias[t][col] = b1 @ W2 + b2 (+ bp @ Me for t==2)
        int k = i - 10;
        int t = k / 5, col = k - t * 5;
        const float *b1, *b2, *W2; int st, of;
        if (col == 0) {
            st = 1; of = 0;
            b1 = t == 0 ? p.c0b1 : t == 1 ? p.c1b1 : p.c2b1;
            b2 = t == 0 ? p.c0b2 : t == 1 ? p.c1b2 : p.c2b2;
            W2 = t == 0 ? p.c0W2 : t == 1 ? p.c1W2 : p.c2W2;
        } else {
            st = A_DIM; of = col - 1;
            b1 = t == 0 ? p.a0b1 : t == 1 ? p.a1b1 : p.a2b1;
            b2 = t == 0 ? p.a0b2 : t == 1 ? p.a1b2 : p.a2b2;
            W2 = t == 0 ? p.a0W2 : t == 1 ? p.a1W2 : p.a2W2;
        }
        float acc = b2[of];
        for (int h = 0; h < H_DIM; h++) acc += b1[h] * W2[h * st + of];
        if (t == 2) {
            const float* bp = (col == 0) ? p.c2bp : p.a2bp;
            for (int e = 0; e < E_DIM; e++) acc += bp[e] * g_W[W_ME_OFF + e * 5 + col];
        }
        g_W[W_B_OFF + k] = acc;
    }
}

// ---------------------------------------------------------------------------
// K3: deterministic scatter of row ids into tid-sorted segments (no atomics)
// ---------------------------------------------------------------------------
__global__ void k_scatter(const int* __restrict__ task) {
    int thr = threadIdx.x;
    int b = blockIdx.x * 256 + thr;
    int t = task[b];
    __shared__ int wc[8][3];
    int w = thr >> 5, lane = thr & 31;
    unsigned m0 = __ballot_sync(~0u, t == 0);
    unsigned m1 = __ballot_sync(~0u, t == 1);
    unsigned m2 = __ballot_sync(~0u, t == 2);
    if (lane == 0) { wc[w][0] = __popc(m0); wc[w][1] = __popc(m1); wc[w][2] = __popc(m2); }
    __syncthreads();
    int pre = 0;
    for (int i = 0; i < w; i++) pre += wc[i][t];
    unsigned mym = (t == 0) ? m0 : (t == 1) ? m1 : m2;
    int rank = pre + __popc(mym & ((1u << lane) - 1));
    g_idx[g_base[blockIdx.x * 3 + t] + rank] = (unsigned)b | ((unsigned)t << 20);
}

// ---------------------------------------------------------------------------
// K4: main — each warp = 4 groups of 8 lanes; each group owns 4 rows of one
//     (warp-uniform) task segment; selected-head folded GEMV, 3-step shfl
//     reduction, leader stores value+logits (+ pointgoal term for head 2).
// ---------------------------------------------------------------------------
__global__ void __launch_bounds__(256) k_main(const float* __restrict__ feat,
                                              const float* __restrict__ pgoal,
                                              float* __restrict__ out) {
    __shared__ float sw[SMEM_W];
    for (int i = threadIdx.x; i < 7705; i += 256) sw[i] = g_W[i];
    __syncthreads();

    int lane = threadIdx.x & 31;
    int warp = blockIdx.x * 8 + (threadIdx.x >> 5);
    int s = lane & 7;                 // feature sub-lane within group
    int q = lane >> 3;                // group index (row-quad)
    int pbase = warp * 16 + q * 4;

    unsigned pk0 = g_idx[pbase + 0];
    unsigned pk1 = g_idx[pbase + 1];
    unsigned pk2 = g_idx[pbase + 2];
    unsigned pk3 = g_idx[pbase + 3];
    unsigned first = (pk0 != SENT) ? pk0 : (pk1 != SENT) ? pk1
                     : (pk2 != SENT) ? pk2 : pk3;
    int t = (first == SENT) ? 0 : (int)(first >> 20);

    unsigned r0 = (pk0 == SENT) ? 0u : (pk0 & 0xFFFFFu);
    unsigned r1 = (pk1 == SENT) ? 0u : (pk1 & 0xFFFFFu);
    unsigned r2 = (pk2 == SENT) ? 0u : (pk2 & 0xFFFFFu);
    unsigned r3 = (pk3 == SENT) ? 0u : (pk3 & 0xFFFFFu);

    const float* wb = &sw[t * 2560];
    const float* p0 = feat + (size_t)r0 * F_DIM + s * 4;
    const float* p1 = feat + (size_t)r1 * F_DIM + s * 4;
    const float* p2 = feat + (size_t)r2 * F_DIM + s * 4;
    const float* p3 = feat + (size_t)r3 * F_DIM + s * 4;

    float acc[4][5];
#pragma unroll
    for (int i = 0; i < 4; i++)
#pragma unroll
        for (int c = 0; c < 5; c++) acc[i][c] = 0.f;

#pragma unroll 4
    for (int j = 0; j < 16; j++) {
        float4 x0 = *reinterpret_cast<const float4*>(p0 + j * 32);
        float4 x1 = *reinterpret_cast<const float4*>(p1 + j * 32);
        float4 x2 = *reinterpret_cast<const float4*>(p2 + j * 32);
        float4 x3 = *reinterpret_cast<const float4*>(p3 + j * 32);
#pragma unroll
        for (int col = 0; col < 5; col++) {
            float4 w = *reinterpret_cast<const float4*>(wb + ((j * 5 + col) * 8 + s) * 4);
            acc[0][col] = fmaf(x0.x, w.x, fmaf(x0.y, w.y, fmaf(x0.z, w.z, fmaf(x0.w, w.w, acc[0][col]))));
            acc[1][col] = fmaf(x1.x, w.x, fmaf(x1.y, w.y, fmaf(x1.z, w.z, fmaf(x1.w, w.w, acc[1][col]))));
            acc[2][col] = fmaf(x2.x, w.x, fmaf(x2.y, w.y, fmaf(x2.z, w.z, fmaf(x2.w, w.w, acc[2][col]))));
            acc[3][col] = fmaf(x3.x, w.x, fmaf(x3.y, w.y, fmaf(x3.z, w.z, fmaf(x3.w, w.w, acc[3][col]))));
        }
    }

    // reduce across the 8 lanes of each group (xor 4,2,1 stays inside a group)
#pragma unroll
    for (int i = 0; i < 4; i++)
#pragma unroll
        for (int c = 0; c < 5; c++) {
            float v = acc[i][c];
            v += __shfl_xor_sync(0xffffffffu, v, 4);
            v += __shfl_xor_sync(0xffffffffu, v, 2);
            v += __shfl_xor_sync(0xffffffffu, v, 1);
            acc[i][c] = v;
        }

    if (s == 0) {
        unsigned pks[4] = {pk0, pk1, pk2, pk3};
        unsigned rws[4] = {r0, r1, r2, r3};
#pragma unroll
        for (int i = 0; i < 4; i++) {
            if (pks[i] == SENT) continue;
            unsigned row = rws[i];
            float o[5];
#pragma unroll
            for (int c = 0; c < 5; c++) o[c] = acc[i][c] + sw[W_B_OFF + t * 5 + c];
            if (t == 2) {
                float2 g = *reinterpret_cast<const float2*>(pgoal + (size_t)row * 2);
#pragma unroll
                for (int c = 0; c < 5; c++)
                    o[c] = fmaf(g.x, sw[W_MP_OFF + c], fmaf(g.y, sw[W_MP_OFF + 5 + c], o[c]));
            }
            float* op = out + (size_t)row * 5;
            op[0] = o[0]; op[1] = o[1]; op[2] = o[2]; op[3] = o[3]; op[4] = o[4];
        }
    }
}

// ---------------------------------------------------------------------------
extern "C" void kernel_launch(void* const* d_in, const int* in_sizes, int n_in,
                              void* d_out, int out_size) {
    (void)in_sizes; (void)n_in; (void)out_size;
    Params p;
    p.features  = (const float*)d_in[0];
    p.pointgoal = (const float*)d_in[1];
    p.a0W1 = (const float*)d_in[2];  p.a0b1 = (const float*)d_in[3];
    p.a0W2 = (const float*)d_in[4];  p.a0b2 = (const float*)d_in[5];
    p.a1W1 = (const float*)d_in[6];  p.a1b1 = (const float*)d_in[7];
    p.a1W2 = (const float*)d_in[8];  p.a1b2 = (const float*)d_in[9];
    p.a2Wp = (const float*)d_in[10]; p.a2bp = (const float*)d_in[11];
    p.a2W1 = (const float*)d_in[12]; p.a2b1 = (const float*)d_in[13];
    p.a2W2 = (const float*)d_in[14]; p.a2b2 = (const float*)d_in[15];
    p.c0W1 = (const float*)d_in[16]; p.c0b1 = (const float*)d_in[17];
    p.c0W2 = (const float*)d_in[18]; p.c0b2 = (const float*)d_in[19];
    p.c1W1 = (const float*)d_in[20]; p.c1b1 = (const float*)d_in[21];
    p.c1W2 = (const float*)d_in[22]; p.c1b2 = (const float*)d_in[23];
    p.c2Wp = (const float*)d_in[24]; p.c2bp = (const float*)d_in[25];
    p.c2W1 = (const float*)d_in[26]; p.c2b1 = (const float*)d_in[27];
    p.c2W2 = (const float*)d_in[28]; p.c2b2 = (const float*)d_in[29];
    p.task = (const int*)d_in[30];

    k_count_prep<<<287, 256>>>(p);          // counts + idx init + fold M/Me
    k_scan_fin<<<1, 256>>>(p);              // segment bases + Mp + bias
    k_scatter<<<256, 256>>>(p.task);        // tid-sorted index list
    k_main<<<513, 256>>>(p.features, p.pointgoal, (float*)d_out);  // GEMV+select
}

// round 9
// speedup vs baseline: 1.2470x; 1.2470x over previous
#include <cuda_runtime.h>
#include <cstdio>

// Problem constants
#define B_ROWS   65536
#define F_DIM    512
#define H_DIM    256
#define A_DIM    4
#define E_DIM    32

#define SENT     0xFFFFFFFFu
#define IDX_LEN  65792           // 65536 + 256 pad
#define W_MP_OFF 7680            // Mp[2][5]
#define W_B_OFF  7690            // bias[3][5]
#define W_ME_OFF 7712            // Me[32][5] scratch (not copied to smem)
#define W_TOTAL  7872
#define SMEM_W   7712            // floats copied to shared (7705 used, padded)

#define GRID_MAIN  444           // 148 SMs * 3 blocks
#define WARPS_MAIN (GRID_MAIN * 8)
#define NCHUNK     4104          // 16 rows per chunk, 4104*16 = 65664 <= 65792

// Scratch (no allocations allowed -> device globals)
__device__ float    g_W[W_TOTAL];
__device__ unsigned g_idx[IDX_LEN];
__device__ int      g_blockCnt[256 * 3];
__device__ int      g_base[256 * 3];
__device__ int      g_work;

struct Params {
    const float *features, *pointgoal;
    const float *a0W1, *a0b1, *a0W2, *a0b2;
    const float *a1W1, *a1b1, *a1W2, *a1b2;
    const float *a2Wp, *a2bp, *a2W1, *a2b1, *a2W2, *a2b2;
    const float *c0W1, *c0b1, *c0W2, *c0b2;
    const float *c1W1, *c1b1, *c1W2, *c1b2;
    const float *c2Wp, *c2bp, *c2W1, *c2b1, *c2W2, *c2b2;
    const int   *task;
};

// 256-length dot: v[h] * w2[h*st] (w2 pre-offset by output column)
__device__ __forceinline__ float dot256(const float* __restrict__ vrow,
                                        const float* __restrict__ w2, int st) {
    float a0 = 0.f, a1 = 0.f, a2 = 0.f, a3 = 0.f;
#pragma unroll 8
    for (int h = 0; h < 256; h += 4) {
        float4 v = *reinterpret_cast<const float4*>(vrow + h);
        a0 = fmaf(v.x, w2[(h + 0) * st], a0);
        a1 = fmaf(v.y, w2[(h + 1) * st], a1);
        a2 = fmaf(v.z, w2[(h + 2) * st], a2);
        a3 = fmaf(v.w, w2[(h + 3) * st], a3);
    }
    return (a0 + a1) + (a2 + a3);
}

// ---------------------------------------------------------------------------
// K1: per-block task histograms + idx sentinel init + fold W1@W2 (M, Me)
//     + bias core b1@W2 + b2 (parallel, well-unrolled — no serial K2 loops)
// blocks [0,256): counting;  blocks [256,287): prefold
// ---------------------------------------------------------------------------
__global__ void k_count_prep(Params p) {
    if (blockIdx.x < 256) {
        int thr = threadIdx.x;
        int b = blockIdx.x * 256 + thr;
        g_idx[b] = SENT;
        if (blockIdx.x == 0) g_idx[65536 + thr] = SENT;
        int t = p.task[b];
        __shared__ int wc[8][3];
        int w = thr >> 5, lane = thr & 31;
        unsigned m0 = __ballot_sync(~0u, t == 0);
        unsigned m1 = __ballot_sync(~0u, t == 1);
        unsigned m2 = __ballot_sync(~0u, t == 2);
        if (lane == 0) { wc[w][0] = __popc(m0); wc[w][1] = __popc(m1); wc[w][2] = __popc(m2); }
        __syncthreads();
        if (thr < 3) {
            int ssum = 0;
#pragma unroll
            for (int i = 0; i < 8; i++) ssum += wc[i][thr];
            g_blockCnt[blockIdx.x * 3 + thr] = ssum;
        }
    } else {
        int idx = (blockIdx.x - 256) * 256 + threadIdx.x;
        if (idx < 7680) {
            // folded M[t][f][col], col 0 = value (critic), cols 1..4 = logits
            int t = idx / 2560;
            int r = idx - t * 2560;
            int f = r / 5, col = r - f * 5;
            const float *W1, *W2; int st, of;
            if (col == 0) {
                W1 = t == 0 ? p.c0W1 : t == 1 ? p.c1W1 : p.c2W1;
                W2 = t == 0 ? p.c0W2 : t == 1 ? p.c1W2 : p.c2W2;
                st = 1; of = 0;
            } else {
                W1 = t == 0 ? p.a0W1 : t == 1 ? p.a1W1 : p.a2W1;
                W2 = t == 0 ? p.a0W2 : t == 1 ? p.a1W2 : p.a2W2;
                st = A_DIM; of = col - 1;
            }
            float v = dot256(W1 + (size_t)f * H_DIM, W2 + of, st);
            // swizzled layout: main kernel's LDS.128 is broadcast/conflict-free
            int j = f >> 5, ss = (f >> 2) & 7, c = f & 3;
            g_W[t * 2560 + ((j * 5 + col) * 8 + ss) * 4 + c] = v;
        } else if (idx < 7840) {
            // Me[e][col]: rows 512..543 of head-2 W1 folded with W2
            int k = idx - 7680;
            int e = k / 5, col = k - e * 5;
            const float* W1 = (col == 0) ? p.c2W1 : p.a2W1;
            const float* W2 = (col == 0) ? p.c2W2 : p.a2W2;
            int st = (col == 0) ? 1 : A_DIM, of = (col == 0) ? 0 : col - 1;
            g_W[W_ME_OFF + e * 5 + col] =
                dot256(W1 + (size_t)(512 + e) * H_DIM, W2 + of, st);
        } else if (idx < 7855) {
            // bias core: b1 @ W2 + b2 (head-2's bp term added in K2)
            int k = idx - 7840;
            int t = k / 5, col = k - t * 5;
            const float *b1, *b2, *W2; int st, of;
            if (col == 0) {
                st = 1; of = 0;
                b1 = t == 0 ? p.c0b1 : t == 1 ? p.c1b1 : p.c2b1;
                b2 = t == 0 ? p.c0b2 : t == 1 ? p.c1b2 : p.c2b2;
                W2 = t == 0 ? p.c0W2 : t == 1 ? p.c1W2 : p.c2W2;
            } else {
                st = A_DIM; of = col - 1;
                b1 = t == 0 ? p.a0b1 : t == 1 ? p.a1b1 : p.a2b1;
                b2 = t == 0 ? p.a0b2 : t == 1 ? p.a1b2 : p.a2b2;
                W2 = t == 0 ? p.a0W2 : t == 1 ? p.a1W2 : p.a2W2;
            }
            g_W[W_B_OFF + k] = b2[of] + dot256(b1, W2 + of, st);
        }
    }
}

// ---------------------------------------------------------------------------
// K2: exclusive scan of per-block counts (segments padded to 16) + finalize
//     Mp = Wp @ Me, add bp@Me to head-2 bias, reset work counter.
//     Only short (32-iter) loops remain here.
// ---------------------------------------------------------------------------
__global__ void k_scan_fin(Params p) {
    __shared__ int sh[256];
    __shared__ int tot[3];
    int i = threadIdx.x;
    int excl[3];
#pragma unroll
    for (int t = 0; t < 3; t++) {
        int v = g_blockCnt[i * 3 + t];
        sh[i] = v;
        __syncthreads();
        int x = v;
        for (int off = 1; off < 256; off <<= 1) {
            int y = (i >= off) ? sh[i - off] : 0;
            __syncthreads();
            x += y;
            sh[i] = x;
            __syncthreads();
        }
        excl[t] = x - v;
        if (i == 255) tot[t] = x;
        __syncthreads();
    }
    int s1 = (tot[0] + 15) & ~15;
    int s2 = s1 + ((tot[1] + 15) & ~15);
    g_base[i * 3 + 0] = excl[0];
    g_base[i * 3 + 1] = s1 + excl[1];
    g_base[i * 3 + 2] = s2 + excl[2];

    if (i < 10) {
        // Mp[pp][col] = sum_e Wp[pp][e] * Me[e][col]
        int pp = i / 5, col = i - pp * 5;
        const float* Wp = ((col == 0) ? p.c2Wp : p.a2Wp) + pp * E_DIM;
        float acc = 0.f;
#pragma unroll
        for (int e = 0; e < E_DIM; e++) acc += Wp[e] * g_W[W_ME_OFF + e * 5 + col];
        g_W[W_MP_OFF + pp * 5 + col] = acc;
    } else if (i < 15) {
        // head-2 bias += bp @ Me
        int col = i - 10;
        const float* bp = (col == 0) ? p.c2bp : p.a2bp;
        float acc = 0.f;
#pragma unroll
        for (int e = 0; e < E_DIM; e++) acc += bp[e] * g_W[W_ME_OFF + e * 5 + col];
        g_W[W_B_OFF + 10 + col] += acc;
    } else if (i == 100) {
        g_work = WARPS_MAIN;  // reset dynamic-chunk counter for k_main
    }
}

// ---------------------------------------------------------------------------
// K3: deterministic scatter of row ids into tid-sorted segments (no atomics)
// ---------------------------------------------------------------------------
__global__ void k_scatter(const int* __restrict__ task) {
    int thr = threadIdx.x;
    int b = blockIdx.x * 256 + thr;
    int t = task[b];
    __shared__ int wc[8][3];
    int w = thr >> 5, lane = thr & 31;
    unsigned m0 = __ballot_sync(~0u, t == 0);
    unsigned m1 = __ballot_sync(~0u, t == 1);
    unsigned m2 = __ballot_sync(~0u, t == 2);
    if (lane == 0) { wc[w][0] = __popc(m0); wc[w][1] = __popc(m1); wc[w][2] = __popc(m2); }
    __syncthreads();
    int pre = 0;
    for (int i = 0; i < w; i++) pre += wc[i][t];
    unsigned mym = (t == 0) ? m0 : (t == 1) ? m1 : m2;
    int rank = pre + __popc(mym & ((1u << lane) - 1));
    g_idx[g_base[blockIdx.x * 3 + t] + rank] = (unsigned)b | ((unsigned)t << 20);
}

// ---------------------------------------------------------------------------
// K4: main — warp = 4 groups of 8 lanes; each group owns 4 rows of one
//     (warp-uniform) task segment. Double-buffered feature loads, dynamic
//     16-row-chunk scheduling off an atomic counter (no wave tail), 3-step
//     shfl reduction, leader stores value+logits (+ pointgoal term, head 2).
// ---------------------------------------------------------------------------
__global__ void __launch_bounds__(256, 3) k_main(const float* __restrict__ feat,
                                                 const float* __restrict__ pgoal,
                                                 float* __restrict__ out) {
    __shared__ float sw[SMEM_W];
    for (int i = threadIdx.x; i < 7705; i += 256) sw[i] = g_W[i];
    __syncthreads();

    int lane = threadIdx.x & 31;
    int s = lane & 7;                 // feature sub-lane within group
    int q = lane >> 3;                // group index (row-quad)
    int chunk = blockIdx.x * 8 + (threadIdx.x >> 5);

    while (chunk < NCHUNK) {
        int pbase = chunk * 16 + q * 4;
        unsigned pk0 = g_idx[pbase + 0];
        unsigned pk1 = g_idx[pbase + 1];
        unsigned pk2 = g_idx[pbase + 2];
        unsigned pk3 = g_idx[pbase + 3];
        unsigned first = (pk0 != SENT) ? pk0 : (pk1 != SENT) ? pk1
                         : (pk2 != SENT) ? pk2 : pk3;
        int t = (first == SENT) ? 0 : (int)(first >> 20);

        unsigned r0 = (pk0 == SENT) ? 0u : (pk0 & 0xFFFFFu);
        unsigned r1 = (pk1 == SENT) ? 0u : (pk1 & 0xFFFFFu);
        unsigned r2 = (pk2 == SENT) ? 0u : (pk2 & 0xFFFFFu);
        unsigned r3 = (pk3 == SENT) ? 0u : (pk3 & 0xFFFFFu);

        const float* wb = &sw[t * 2560];
        const float* p0 = feat + (size_t)r0 * F_DIM + s * 4;
        const float* p1 = feat + (size_t)r1 * F_DIM + s * 4;
        const float* p2 = feat + (size_t)r2 * F_DIM + s * 4;
        const float* p3 = feat + (size_t)r3 * F_DIM + s * 4;

        float acc[4][5];
#pragma unroll
        for (int i = 0; i < 4; i++)
#pragma unroll
            for (int c = 0; c < 5; c++) acc[i][c] = 0.f;

        // double-buffered mainloop: next iteration's loads in flight while
        // computing the current one
        float4 xa0 = *reinterpret_cast<const float4*>(p0);
        float4 xa1 = *reinterpret_cast<const float4*>(p1);
        float4 xa2 = *reinterpret_cast<const float4*>(p2);
        float4 xa3 = *reinterpret_cast<const float4*>(p3);
#pragma unroll
        for (int j = 0; j < 16; j++) {
            float4 xb0 = xa0, xb1 = xa1, xb2 = xa2, xb3 = xa3;  // dead at j==15
            if (j < 15) {
                xb0 = *reinterpret_cast<const float4*>(p0 + (j + 1) * 32);
                xb1 = *reinterpret_cast<const float4*>(p1 + (j + 1) * 32);
                xb2 = *reinterpret_cast<const float4*>(p2 + (j + 1) * 32);
                xb3 = *reinterpret_cast<const float4*>(p3 + (j + 1) * 32);
            }
#pragma unroll
            for (int col = 0; col < 5; col++) {
                float4 w = *reinterpret_cast<const float4*>(wb + ((j * 5 + col) * 8 + s) * 4);
                acc[0][col] = fmaf(xa0.x, w.x, fmaf(xa0.y, w.y, fmaf(xa0.z, w.z, fmaf(xa0.w, w.w, acc[0][col]))));
                acc[1][col] = fmaf(xa1.x, w.x, fmaf(xa1.y, w.y, fmaf(xa1.z, w.z, fmaf(xa1.w, w.w, acc[1][col]))));
                acc[2][col] = fmaf(xa2.x, w.x, fmaf(xa2.y, w.y, fmaf(xa2.z, w.z, fmaf(xa2.w, w.w, acc[2][col]))));
                acc[3][col] = fmaf(xa3.x, w.x, fmaf(xa3.y, w.y, fmaf(xa3.z, w.z, fmaf(xa3.w, w.w, acc[3][col]))));
            }
            xa0 = xb0; xa1 = xb1; xa2 = xb2; xa3 = xb3;
        }

        // grab next chunk early so ATOMG latency hides under the reduction
        int nxt = NCHUNK;
        if (lane == 0) nxt = atomicAdd(&g_work, 1);

        // reduce across the 8 lanes of each group (xor 4,2,1 stays in-group)
#pragma unroll
        for (int i = 0; i < 4; i++)
#pragma unroll
            for (int c = 0; c < 5; c++) {
                float v = acc[i][c];
                v += __shfl_xor_sync(0xffffffffu, v, 4);
                v += __shfl_xor_sync(0xffffffffu, v, 2);
                v += __shfl_xor_sync(0xffffffffu, v, 1);
                acc[i][c] = v;
            }

        if (s == 0) {
            unsigned pks[4] = {pk0, pk1, pk2, pk3};
            unsigned rws[4] = {r0, r1, r2, r3};
#pragma unroll
            for (int i = 0; i < 4; i++) {
                if (pks[i] == SENT) continue;
                unsigned row = rws[i];
                float o[5];
#pragma unroll
                for (int c = 0; c < 5; c++) o[c] = acc[i][c] + sw[W_B_OFF + t * 5 + c];
                if (t == 2) {
                    float2 g = *reinterpret_cast<const float2*>(pgoal + (size_t)row * 2);
#pragma unroll
                    for (int c = 0; c < 5; c++)
                        o[c] = fmaf(g.x, sw[W_MP_OFF + c], fmaf(g.y, sw[W_MP_OFF + 5 + c], o[c]));
                }
                float* op = out + (size_t)row * 5;
                op[0] = o[0]; op[1] = o[1]; op[2] = o[2]; op[3] = o[3]; op[4] = o[4];
            }
        }

        chunk = __shfl_sync(0xffffffffu, nxt, 0);
    }
}

// ---------------------------------------------------------------------------
extern "C" void kernel_launch(void* const* d_in, const int* in_sizes, int n_in,
                              void* d_out, int out_size) {
    (void)in_sizes; (void)n_in; (void)out_size;
    Params p;
    p.features  = (const float*)d_in[0];
    p.pointgoal = (const float*)d_in[1];
    p.a0W1 = (const float*)d_in[2];  p.a0b1 = (const float*)d_in[3];
    p.a0W2 = (const float*)d_in[4];  p.a0b2 = (const float*)d_in[5];
    p.a1W1 = (const float*)d_in[6];  p.a1b1 = (const float*)d_in[7];
    p.a1W2 = (const float*)d_in[8];  p.a1b2 = (const float*)d_in[9];
    p.a2Wp = (const float*)d_in[10]; p.a2bp = (const float*)d_in[11];
    p.a2W1 = (const float*)d_in[12]; p.a2b1 = (const float*)d_in[13];
    p.a2W2 = (const float*)d_in[14]; p.a2b2 = (const float*)d_in[15];
    p.c0W1 = (const float*)d_in[16]; p.c0b1 = (const float*)d_in[17];
    p.c0W2 = (const float*)d_in[18]; p.c0b2 = (const float*)d_in[19];
    p.c1W1 = (const float*)d_in[20]; p.c1b1 = (const float*)d_in[21];
    p.c1W2 = (const float*)d_in[22]; p.c1b2 = (const float*)d_in[23];
    p.c2Wp = (const float*)d_in[24]; p.c2bp = (const float*)d_in[25];
    p.c2W1 = (const float*)d_in[26]; p.c2b1 = (const float*)d_in[27];
    p.c2W2 = (const float*)d_in[28]; p.c2b2 = (const float*)d_in[29];
    p.task = (const int*)d_in[30];

    k_count_prep<<<287, 256>>>(p);             // counts + idx init + folds + bias core
    k_scan_fin<<<1, 256>>>(p);                 // bases + Mp + bias finish + work reset
    k_scatter<<<256, 256>>>(p.task);           // tid-sorted index list
    k_main<<<GRID_MAIN, 256>>>(p.features, p.pointgoal, (float*)d_out);
}